// round 17
// baseline (speedup 1.0000x reference)
#include <cuda_runtime.h>
#include <cuda_bf16.h>
#include <cuda_fp16.h>
#include <math.h>

#define BB 8
#define LL 2048
#define HH 256
#define MTOT (BB*LL)
#define NITEMS 512

// Projected tensors: single fp16. Row-major [b*L][H].
__device__ __align__(16) __half g_Q[MTOT*HH];
__device__ __align__(16) __half g_K[MTOT*HH];
__device__ __align__(16) __half g_V[MTOT*HH];
// Pre-converted fp16 weights [3][H][H].
__device__ __align__(16) __half g_Wh[3*HH*HH];

// Split-K partials per 8-tile chunk (<=4), plus work counter / tickets.
__device__ __align__(16) float g_Op[4][MTOT*HH];
__device__ float g_lp[4][MTOT];
__device__ int g_ctr;
__device__ int g_tk[128];

// ---------------- helpers ----------------
__device__ __forceinline__ unsigned smem_u32(const void* p) {
    unsigned a;
    asm("{ .reg .u64 t; cvta.to.shared.u64 t, %1; cvt.u32.u64 %0, t; }" : "=r"(a) : "l"(p));
    return a;
}
__device__ __forceinline__ unsigned packf2(float e0, float e1) {
    unsigned r;  // low half = e0, high half = e1
    asm("cvt.rn.f16x2.f32 %0, %1, %2;" : "=r"(r) : "f"(e1), "f"(e0));
    return r;
}
__device__ __forceinline__ float ex2(float x) {
    float r;
    asm("ex2.approx.f32 %0, %1;" : "=f"(r) : "f"(x));
    return r;
}
__device__ __forceinline__ void ldsm4(unsigned* r, unsigned addr) {
    asm volatile("ldmatrix.sync.aligned.m8n8.x4.shared.b16 {%0,%1,%2,%3}, [%4];"
                 : "=r"(r[0]), "=r"(r[1]), "=r"(r[2]), "=r"(r[3]) : "r"(addr));
}
__device__ __forceinline__ void ldsm4t(unsigned* r, unsigned addr) {
    asm volatile("ldmatrix.sync.aligned.m8n8.x4.trans.shared.b16 {%0,%1,%2,%3}, [%4];"
                 : "=r"(r[0]), "=r"(r[1]), "=r"(r[2]), "=r"(r[3]) : "r"(addr));
}
__device__ __forceinline__ void mmah(float* c, const unsigned* a, unsigned b0, unsigned b1) {
    asm volatile(
        "mma.sync.aligned.m16n8k16.row.col.f32.f16.f16.f32 "
        "{%0,%1,%2,%3},{%4,%5,%6,%7},{%8,%9},{%0,%1,%2,%3};"
        : "+f"(c[0]), "+f"(c[1]), "+f"(c[2]), "+f"(c[3])
        : "r"(a[0]), "r"(a[1]), "r"(a[2]), "r"(a[3]), "r"(b0), "r"(b1));
}
__device__ __forceinline__ void cp16(unsigned dst, const void* src) {
    asm volatile("cp.async.cg.shared.global [%0], [%1], 16;" :: "r"(dst), "l"(src) : "memory");
}
__device__ __forceinline__ void cp_commit() { asm volatile("cp.async.commit_group;" ::: "memory"); }
__device__ __forceinline__ void cp_wait0()  { asm volatile("cp.async.wait_group 0;"  ::: "memory"); }
__device__ __forceinline__ void cp_wait1()  { asm volatile("cp.async.wait_group 1;"  ::: "memory"); }

// smem tile layout: rows of 256 x 16-bit = 512B = 32 16B-chunks, XOR swizzle.
__device__ __forceinline__ unsigned tswz(int r, int c8) {
    return (unsigned)(r * 512 + ((c8 ^ (r & 7)) << 4));
}

// attention smem layout: Q 64KB; K double-buffer 2x32KB; V double-buffer 2x32KB
#define SM_Q   0
#define SM_K0  65536
#define SM_K1  98304
#define SM_V0  131072
#define SM_V1  163840
#define SMEM_TOTAL 196608

// qkv smem layout: X fp16 64KB; W fp16 double-buffer 2x32KB
#define QK_X   0
#define QK_W0  65536
#define QK_W1  98304
#define QKV_SMEM 131072

// ---------------------------------------------------------------------------
// W pre-convert (fp32 -> fp16) + zero the attn work counter / tickets.
// ---------------------------------------------------------------------------
__global__ __launch_bounds__(256) void wconv_kernel(
    const float* __restrict__ Wq,
    const float* __restrict__ Wk,
    const float* __restrict__ Wv)
{
    const int idx = blockIdx.x * 256 + threadIdx.x;   // 8 floats per thread
    const int z = idx >> 13;                           // 8192 threads per matrix
    const int r = idx & 8191;
    const float* W = (z == 0) ? Wq : (z == 1) ? Wk : Wv;
    const float* src = W + (size_t)r * 8;
    float4 a = *(const float4*)src;
    float4 c = *(const float4*)(src + 4);
    *(uint4*)(g_Wh + (size_t)z * HH * HH + (size_t)r * 8) =
        make_uint4(packf2(a.x, a.y), packf2(a.z, a.w),
                   packf2(c.x, c.y), packf2(c.z, c.w));
    if (blockIdx.x == 0) {
        if (threadIdx.x < 128) g_tk[threadIdx.x] = 0;
        if (threadIdx.x == 128) g_ctr = 0;
    }
}

// ---------------------------------------------------------------------------
// QKV projection: X single fp16 (converted in-kernel), W fp16 pre-converted,
// double-buffered via cp.async. 12 output tiles per CTA of 128 X-rows.
// ---------------------------------------------------------------------------
__global__ __launch_bounds__(256, 1) void qkv_mma_kernel(const float* __restrict__ X)
{
    extern __shared__ char smc[];
    const unsigned sb = smem_u32(smc);
    const int tid = threadIdx.x;
    const int w   = tid >> 5;
    const int l   = tid & 31;
    const int m0  = blockIdx.x * 128;

    // ---- prologue: W tile 0 (fp16) into buf0 ----
    #pragma unroll
    for (int it = 0; it < 8; it++) {
        int v = tid + it * 256;
        int r = v >> 5, c8 = v & 31;
        cp16(sb + QK_W0 + tswz(r, c8), g_Wh + (size_t)r * HH + c8 * 8);
    }
    cp_commit();

    // ---- X tile -> single fp16, swizzled (overlaps W cp.async) ----
    #pragma unroll
    for (int it = 0; it < 16; it++) {
        int v = tid + it * 256;
        int r = v >> 5, c8 = v & 31;
        const float* src = X + (size_t)(m0 + r) * HH + c8 * 8;
        float4 a = *(const float4*)src;
        float4 c = *(const float4*)(src + 4);
        *(uint4*)(smc + QK_X + tswz(r, c8)) =
            make_uint4(packf2(a.x, a.y), packf2(a.z, a.w),
                       packf2(c.x, c.y), packf2(c.z, c.w));
    }

    const int qrow = (w << 4) + (l & 15);
    const int qx   = l >> 4;
    const int qsw  = qrow & 7;
    const unsigned xb = QK_X + (unsigned)qrow * 512;
    const int krl  = ((l & 16) >> 1) + (l & 7);
    const int kcp  = (l >> 3) & 1;

    #pragma unroll 1
    for (int t = 0; t < 12; t++) {
        const unsigned wbuf = (t & 1) ? QK_W1 : QK_W0;

        // ---- prefetch W(t+1) into the other buffer ----
        if (t + 1 < 12) {
            const unsigned wn = (t & 1) ? QK_W0 : QK_W1;
            const __half* src = g_Wh + (size_t)((t + 1) >> 2) * HH * HH
                                     + (size_t)(((t + 1) & 3) * 64) * HH;
            #pragma unroll
            for (int it = 0; it < 8; it++) {
                int v = tid + it * 256;
                int r = v >> 5, c8 = v & 31;
                cp16(sb + wn + tswz(r, c8), src + (size_t)r * HH + c8 * 8);
            }
        }
        cp_commit();
        cp_wait1();          // W(t) ready; W(t+1) may be in flight
        __syncthreads();

        // ---- MMA: Y = X * W^T ----
        float c[8][4];
        #pragma unroll
        for (int j = 0; j < 8; j++)
            #pragma unroll
            for (int e = 0; e < 4; e++) c[j][e] = 0.f;

        #pragma unroll 8
        for (int ks = 0; ks < 16; ks++) {
            unsigned ax[4];
            int ach = 2 * ks + qx;
            ldsm4(ax, sb + xb + ((unsigned)((ach ^ qsw) << 4)));
            #pragma unroll
            for (int j2 = 0; j2 < 4; j2++) {
                unsigned bh[4];
                ldsm4(bh, sb + wbuf + tswz((j2 << 4) + krl, 2 * ks + kcp));
                mmah(c[2*j2],   ax, bh[0], bh[1]);
                mmah(c[2*j2+1], ax, bh[2], bh[3]);
            }
        }

        // ---- epilogue: single fp16 ----
        __half* Y = ((t >> 2) == 0) ? g_Q : ((t >> 2) == 1) ? g_K : g_V;
        const int row0 = m0 + (w << 4) + (l >> 2);
        const int col  = (t & 3) * 64 + 2 * (l & 3);
        #pragma unroll
        for (int j = 0; j < 8; j++) {
            size_t base0 = (size_t)row0 * HH + col + j * 8;
            size_t base1 = base0 + (size_t)8 * HH;
            *(unsigned*)(Y + base0) = packf2(c[j][0], c[j][1]);
            *(unsigned*)(Y + base1) = packf2(c[j][2], c[j][3]);
        }
        __syncthreads();     // all warps done with wbuf before it is refilled
    }
}

// ---------------------------------------------------------------------------
// fp16 flash attention, no-max softmax, persistent CTAs + dynamic work queue.
// Item = (q-tile, batch, 8-key-tile chunk); partials merged inline by the
// last-ticket CTA in fixed chunk order (deterministic).
// ---------------------------------------------------------------------------
__global__ __launch_bounds__(256, 1) void attn_kernel(
    const int* __restrict__ lens,
    float* __restrict__ out)
{
    extern __shared__ char smc[];
    __shared__ int sh_bcast;
    const unsigned sb = smem_u32(smc);
    const int tid = threadIdx.x;
    const int w   = tid >> 5;
    const int l   = tid & 31;

    // lane constants (item-independent)
    const int qrow = (w << 4) + (l & 15);
    const int qx   = l >> 4;
    const int qsw  = qrow & 7;
    const unsigned qb = SM_Q + (unsigned)qrow * 512;
    const int krl  = ((l & 16) >> 1) + (l & 7);
    const int kcp  = (l >> 3) & 1;
    const int vrl  = (((l >> 3) & 1) << 3) + (l & 7);
    const int vco  = l >> 4;
    const float SC2 = 0.0625f * 1.4426950408889634f;  // 1/sqrt(256)*log2(e)

    int prev_pair = -1;

    for (;;) {
        __syncthreads();
        if (tid == 0) sh_bcast = atomicAdd(&g_ctr, 1);
        __syncthreads();
        const int item = sh_bcast;
        if (item >= NITEMS) { cp_wait0(); break; }

        const int c   = item >> 7;        // chunk-major ordering
        const int p   = item & 127;
        const int b   = p >> 4;
        const int q0  = (p & 15) << 7;
        const int len = lens[b];
        const int nkt = (len + 63) >> 6;
        const int t0  = c << 3;
        if (t0 >= nkt) continue;
        const int t1  = (t0 + 8 < nkt) ? (t0 + 8) : nkt;

        const __half* gK = g_K + (size_t)b * LL * HH;
        const __half* gV = g_V + (size_t)b * LL * HH;

        // ---- prologue: (Q if pair changed) + K(t0), V(t0) in one group ----
        if (p != prev_pair) {
            const __half* q = g_Q + (size_t)(b * LL + q0) * HH;
            #pragma unroll
            for (int it = 0; it < 16; it++) {
                int v = tid + it * 256;
                int r = v >> 5, c8 = v & 31;
                cp16(sb + SM_Q + tswz(r, c8), q + r * HH + c8 * 8);
            }
        }
        prev_pair = p;
        {
            const unsigned kb0 = (t0 & 1) ? SM_K1 : SM_K0;
            const unsigned vb0 = (t0 & 1) ? SM_V1 : SM_V0;
            const __half* k0p = gK + (size_t)(t0 << 6) * HH;
            const __half* v0p = gV + (size_t)(t0 << 6) * HH;
            #pragma unroll
            for (int it = 0; it < 8; it++) {
                int v = tid + it * 256;
                int r = v >> 5, c8 = v & 31;
                unsigned off = tswz(r, c8);
                cp16(sb + kb0 + off, k0p + r * HH + c8 * 8);
                cp16(sb + vb0 + off, v0p + r * HH + c8 * 8);
            }
        }
        cp_commit();

        float o[32][4];
        #pragma unroll
        for (int n = 0; n < 32; n++)
            #pragma unroll
            for (int e = 0; e < 4; e++) o[n][e] = 0.f;
        float rs0 = 0.f, rs1 = 0.f;

        for (int kt = t0; kt < t1; kt++) {
            const int k0 = kt << 6;
            const unsigned kbuf = (kt & 1) ? SM_K1 : SM_K0;
            const unsigned vbuf = (kt & 1) ? SM_V1 : SM_V0;

            // ---- prefetch K(t+1), V(t+1) ----
            if (kt + 1 < t1) {
                const unsigned kn = (kt & 1) ? SM_K0 : SM_K1;
                const unsigned vn = (kt & 1) ? SM_V0 : SM_V1;
                const __half* kh = gK + (size_t)(k0 + 64) * HH;
                const __half* vh = gV + (size_t)(k0 + 64) * HH;
                #pragma unroll
                for (int it = 0; it < 8; it++) {
                    int v = tid + it * 256;
                    int r = v >> 5, c8 = v & 31;
                    unsigned off = tswz(r, c8);
                    cp16(sb + kn + off, kh + r * HH + c8 * 8);
                    cp16(sb + vn + off, vh + r * HH + c8 * 8);
                }
            }
            cp_commit();
            cp_wait1();
            __syncthreads();

            // ---- S = Q K^T ----
            float s[8][4];
            #pragma unroll
            for (int j = 0; j < 8; j++)
                #pragma unroll
                for (int e = 0; e < 4; e++) s[j][e] = 0.f;

            #pragma unroll 8
            for (int ks = 0; ks < 16; ks++) {
                unsigned ah[4];
                int ach = 2 * ks + qx;
                ldsm4(ah, sb + qb + ((unsigned)((ach ^ qsw) << 4)));
                #pragma unroll
                for (int j2 = 0; j2 < 4; j2++) {
                    unsigned bh[4];
                    ldsm4(bh, sb + kbuf + tswz((j2 << 4) + krl, 2 * ks + kcp));
                    mmah(s[2*j2],   ah, bh[0], bh[1]);
                    mmah(s[2*j2+1], ah, bh[2], bh[3]);
                }
            }

            // ---- softmax (registers; P single fp16) ----
            unsigned aph[4][4];
            if (k0 + 64 <= len) {
                #pragma unroll
                for (int kk = 0; kk < 4; kk++) {
                    #pragma unroll
                    for (int h = 0; h < 2; h++) {
                        int j = 2 * kk + h;
                        float p0 = ex2(s[j][0] * SC2);
                        float p1 = ex2(s[j][1] * SC2);
                        float p2 = ex2(s[j][2] * SC2);
                        float p3 = ex2(s[j][3] * SC2);
                        rs0 += p0 + p1;
                        rs1 += p2 + p3;
                        aph[kk][2*h+0] = packf2(p0, p1);
                        aph[kk][2*h+1] = packf2(p2, p3);
                    }
                }
            } else {
                #pragma unroll
                for (int kk = 0; kk < 4; kk++) {
                    #pragma unroll
                    for (int h = 0; h < 2; h++) {
                        int j = 2 * kk + h;
                        int col = k0 + 8 * j + 2 * (l & 3);
                        float p0 = (col     < len) ? ex2(s[j][0] * SC2) : 0.f;
                        float p1 = (col + 1 < len) ? ex2(s[j][1] * SC2) : 0.f;
                        float p2 = (col     < len) ? ex2(s[j][2] * SC2) : 0.f;
                        float p3 = (col + 1 < len) ? ex2(s[j][3] * SC2) : 0.f;
                        rs0 += p0 + p1;
                        rs1 += p2 + p3;
                        aph[kk][2*h+0] = packf2(p0, p1);
                        aph[kk][2*h+1] = packf2(p2, p3);
                    }
                }
            }

            // ---- O += P V ----
            #pragma unroll
            for (int kk = 0; kk < 4; kk++) {
                #pragma unroll
                for (int j2 = 0; j2 < 16; j2++) {
                    unsigned vh[4];
                    ldsm4t(vh, sb + vbuf + tswz((kk << 4) + vrl, 2 * j2 + vco));
                    mmah(o[2*j2],   aph[kk], vh[0], vh[1]);
                    mmah(o[2*j2+1], aph[kk], vh[2], vh[3]);
                }
            }
            __syncthreads();
        }

        // ---- write partial (O, l) for chunk c ----
        rs0 += __shfl_xor_sync(0xffffffffu, rs0, 1);
        rs0 += __shfl_xor_sync(0xffffffffu, rs0, 2);
        rs1 += __shfl_xor_sync(0xffffffffu, rs1, 1);
        rs1 += __shfl_xor_sync(0xffffffffu, rs1, 2);

        const int row0g = b * LL + q0 + (w << 4) + (l >> 2);
        const int row1g = row0g + 8;
        const int colb  = 2 * (l & 3);
        {
            float* o0 = g_Op[c] + (size_t)row0g * HH + colb;
            float* o1 = g_Op[c] + (size_t)row1g * HH + colb;
            #pragma unroll
            for (int n = 0; n < 32; n++) {
                *(float2*)(o0 + 8 * n) = make_float2(o[n][0], o[n][1]);
                *(float2*)(o1 + 8 * n) = make_float2(o[n][2], o[n][3]);
            }
            if ((l & 3) == 0) {
                g_lp[c][row0g] = rs0;
                g_lp[c][row1g] = rs1;
            }
        }
        __threadfence();
        __syncthreads();
        if (tid == 0) sh_bcast = atomicAdd(&g_tk[p], 1);
        __syncthreads();

        const int np = (nkt + 7) >> 3;
        if (sh_bcast == np - 1) {
            // ---- deterministic merge: read chunks 0..np-1 in fixed order ----
            __threadfence();
            float l0 = 0.f, l1 = 0.f;
            #pragma unroll
            for (int n = 0; n < 32; n++)
                #pragma unroll
                for (int e = 0; e < 4; e++) o[n][e] = 0.f;
            #pragma unroll 1
            for (int c2 = 0; c2 < np; c2++) {
                l0 += g_lp[c2][row0g];
                l1 += g_lp[c2][row1g];
                const float* s0 = g_Op[c2] + (size_t)row0g * HH + colb;
                const float* s1 = g_Op[c2] + (size_t)row1g * HH + colb;
                #pragma unroll
                for (int n = 0; n < 32; n++) {
                    float2 a = *(const float2*)(s0 + 8 * n);
                    float2 d = *(const float2*)(s1 + 8 * n);
                    o[n][0] += a.x; o[n][1] += a.y;
                    o[n][2] += d.x; o[n][3] += d.y;
                }
            }
            const float inv0 = 1.f / l0;
            const float inv1 = 1.f / l1;
            float* d0 = out + (size_t)row0g * HH + colb;
            float* d1 = out + (size_t)row1g * HH + colb;
            #pragma unroll
            for (int n = 0; n < 32; n++) {
                *(float2*)(d0 + 8 * n) = make_float2(o[n][0] * inv0, o[n][1] * inv0);
                *(float2*)(d1 + 8 * n) = make_float2(o[n][2] * inv1, o[n][3] * inv1);
            }
        }
    }
}

// ---------------------------------------------------------------------------
extern "C" void kernel_launch(void* const* d_in, const int* in_sizes, int n_in,
                              void* d_out, int out_size)
{
    const float* X    = (const float*)d_in[0];
    const float* Wq   = (const float*)d_in[1];
    const float* Wk   = (const float*)d_in[2];
    const float* Wv   = (const float*)d_in[3];
    const int*   lens = (const int*)d_in[4];
    float* out = (float*)d_out;

    wconv_kernel<<<dim3(96), 256>>>(Wq, Wk, Wv);

    cudaFuncSetAttribute(qkv_mma_kernel,
                         cudaFuncAttributeMaxDynamicSharedMemorySize, QKV_SMEM);
    qkv_mma_kernel<<<dim3(MTOT / 128), 256, QKV_SMEM>>>(X);

    cudaFuncSetAttribute(attn_kernel,
                         cudaFuncAttributeMaxDynamicSharedMemorySize, SMEM_TOTAL);
    attn_kernel<<<dim3(148), 256, SMEM_TOTAL>>>(lens, out);
}